// round 1
// baseline (speedup 1.0000x reference)
#include <cuda_runtime.h>
#include <math.h>

#define NN    1500
#define NE    48000
#define ET    (NE + NN)       // edges + self loops = 49500
#define INF_DIM 128
#define OUTC  32
#define HEADS 4
#define HC    128             // HEADS*OUTC
#define EDIM  16

// ---------------- scratch (device globals; no allocation allowed) ----------
__device__ float g_cnt[NN];
__device__ float g_easum[NN * EDIM];
__device__ float g_weatt[EDIM * HEADS];
__device__ float g_h[NN * HC];          // h1, then reused for h2
__device__ float g_as[NN * HEADS];
__device__ float g_ad[NN * HEADS];
__device__ float g_alpha[ET * HEADS];   // alpha -> exp -> normalized weight
__device__ float g_m[NN * HEADS];
__device__ float g_s[NN * HEADS];
__device__ float g_agg[NN * HC];
__device__ float g_x1[NN * OUTC];
__device__ float g_x2[NN * OUTC];

__device__ __forceinline__ void atomicMaxFloat(float* addr, float val) {
    int old = __float_as_int(*addr);
    while (__int_as_float(old) < val) {
        int assumed = old;
        old = atomicCAS((int*)addr, assumed, __float_as_int(val));
        if (old == assumed) break;
    }
}

// ---------------- kernels --------------------------------------------------

// zero cnt/easum/agg/s, m = -inf
__global__ void k_init() {
    int i = blockIdx.x * blockDim.x + threadIdx.x;
    if (i < NN * HC)   g_agg[i] = 0.f;
    if (i < NN)        g_cnt[i] = 0.f;
    if (i < NN * EDIM) g_easum[i] = 0.f;
    if (i < NN * HEADS) { g_s[i] = 0.f; g_m[i] = -1e30f; }
}

// re-init between layers (agg, s, m)
__global__ void k_reinit() {
    int i = blockIdx.x * blockDim.x + threadIdx.x;
    if (i < NN * HC)    g_agg[i] = 0.f;
    if (i < NN * HEADS) { g_s[i] = 0.f; g_m[i] = -1e30f; }
}

// per-dst edge-feature sums + counts (for self-loop attr fill_value='mean')
__global__ void k_prep(const int* __restrict__ edges, const float* __restrict__ ef) {
    int t = blockIdx.x * blockDim.x + threadIdx.x;
    if (t >= NE * EDIM) return;
    int e = t / EDIM, d = t % EDIM;
    int dst = edges[NE + e];
    atomicAdd(&g_easum[dst * EDIM + d], ef[e * EDIM + d]);
    if (d == 0) atomicAdd(&g_cnt[dst], 1.f);
}

// We_att[d][h] = sum_c We[d][h*32+c] * att_e[h][c]
__global__ void k_weatt(const float* __restrict__ We, const float* __restrict__ att_e) {
    int t = blockIdx.x * blockDim.x + threadIdx.x;
    if (t >= EDIM * HEADS) return;
    int d = t / HEADS, h = t % HEADS;
    float acc = 0.f;
    #pragma unroll
    for (int c = 0; c < OUTC; c++)
        acc += We[d * HC + h * OUTC + c] * att_e[h * OUTC + c];
    g_weatt[d * HEADS + h] = acc;
}

// g_h[i][j] = sum_k in[i*K+k] * W[k*128+j]   (out width fixed at HC=128)
__global__ void k_proj(const float* __restrict__ in, const float* __restrict__ W, int K) {
    int t = blockIdx.x * blockDim.x + threadIdx.x;
    if (t >= NN * HC) return;
    int i = t / HC, j = t % HC;
    const float* xr = in + i * K;
    float acc = 0.f;
    for (int k = 0; k < K; k++)
        acc = fmaf(xr[k], W[k * HC + j], acc);
    g_h[t] = acc;
}

// per-node attention dot products
__global__ void k_attdot(const float* __restrict__ a_src, const float* __restrict__ a_dst) {
    int t = blockIdx.x * blockDim.x + threadIdx.x;
    if (t >= NN * HEADS) return;
    int i = t / HEADS, h = t % HEADS;
    float s = 0.f, d = 0.f;
    #pragma unroll
    for (int c = 0; c < OUTC; c++) {
        float v = g_h[i * HC + h * OUTC + c];
        s = fmaf(v, a_src[h * OUTC + c], s);
        d = fmaf(v, a_dst[h * OUTC + c], d);
    }
    g_as[t] = s;
    g_ad[t] = d;
}

// alpha per (edge, head): src/dst dots (+ optional edge term), leaky relu, seg-max
__global__ void k_alpha(const int* __restrict__ edges, const float* __restrict__ ef,
                        int has_extra) {
    int t = blockIdx.x * blockDim.x + threadIdx.x;
    if (t >= ET * HEADS) return;
    int idx = t / HEADS, h = t % HEADS;
    int src, dst;
    float extra = 0.f;
    if (idx < NE) {
        src = edges[idx]; dst = edges[NE + idx];
        if (has_extra) {
            #pragma unroll
            for (int d = 0; d < EDIM; d++)
                extra = fmaf(ef[idx * EDIM + d], g_weatt[d * HEADS + h], extra);
        }
    } else {
        src = dst = idx - NE;
        if (has_extra) {
            float inv = 1.f / fmaxf(g_cnt[dst], 1.f);
            #pragma unroll
            for (int d = 0; d < EDIM; d++)
                extra = fmaf(g_easum[dst * EDIM + d] * inv, g_weatt[d * HEADS + h], extra);
        }
    }
    float a = g_as[src * HEADS + h] + g_ad[dst * HEADS + h] + extra;
    a = (a > 0.f) ? a : 0.2f * a;   // leaky_relu, slope 0.2
    g_alpha[t] = a;
    atomicMaxFloat(&g_m[dst * HEADS + h], a);
}

// e = exp(alpha - m[dst]); seg-sum into s
__global__ void k_exp(const int* __restrict__ edges) {
    int t = blockIdx.x * blockDim.x + threadIdx.x;
    if (t >= ET * HEADS) return;
    int idx = t / HEADS, h = t % HEADS;
    int dst = (idx < NE) ? edges[NE + idx] : (idx - NE);
    float e = expf(g_alpha[t] - g_m[dst * HEADS + h]);
    g_alpha[t] = e;
    atomicAdd(&g_s[dst * HEADS + h], e);
}

// normalize: w = e / s[dst]
__global__ void k_norm(const int* __restrict__ edges) {
    int t = blockIdx.x * blockDim.x + threadIdx.x;
    if (t >= ET * HEADS) return;
    int idx = t / HEADS, h = t % HEADS;
    int dst = (idx < NE) ? edges[NE + idx] : (idx - NE);
    g_alpha[t] = g_alpha[t] / g_s[dst * HEADS + h];
}

// agg[dst][c] += w[idx][h(c)] * h[src][c]
__global__ void k_agg(const int* __restrict__ edges) {
    int t = blockIdx.x * blockDim.x + threadIdx.x;
    if (t >= ET * HC) return;
    int idx = t / HC, c = t % HC;
    int h = c >> 5;
    int src, dst;
    if (idx < NE) { src = edges[idx]; dst = edges[NE + idx]; }
    else          { src = dst = idx - NE; }
    float w = g_alpha[idx * HEADS + h];
    atomicAdd(&g_agg[dst * HC + c], w * g_h[src * HC + c]);
}

// x[i][c] = mean over heads of agg + bias
__global__ void k_meanbias(const float* __restrict__ bias, float* __restrict__ xout) {
    int t = blockIdx.x * blockDim.x + threadIdx.x;
    if (t >= NN * OUTC) return;
    int i = t / OUTC, c = t % OUTC;
    const float* a = g_agg + i * HC;
    xout[t] = 0.25f * (a[c] + a[OUTC + c] + a[2 * OUTC + c] + a[3 * OUTC + c]) + bias[c];
}

// fill full output with the constant row softmax(relu(fc1_b)@fc2_w + fc2_b)
__global__ void k_fill(const float* __restrict__ fc1_b, const float* __restrict__ fc2_w,
                       const float* __restrict__ fc2_b, float* __restrict__ out) {
    int t = blockIdx.x * blockDim.x + threadIdx.x;
    int total = (NN * NN * 2) / 4;   // float4 per thread (2 rows)
    if (t >= total) return;
    float z0 = fc2_b[0], z1 = fc2_b[1];
    #pragma unroll
    for (int c = 0; c < 32; c++) {
        float hc = fmaxf(fc1_b[c], 0.f);
        z0 = fmaf(hc, fc2_w[c * 2 + 0], z0);
        z1 = fmaf(hc, fc2_w[c * 2 + 1], z1);
    }
    float mm = fmaxf(z0, z1);
    float e0 = expf(z0 - mm), e1 = expf(z1 - mm);
    float inv = 1.f / (e0 + e1);
    float4 v = make_float4(e0 * inv, e1 * inv, e0 * inv, e1 * inv);
    reinterpret_cast<float4*>(out)[t] = v;
}

// per-edge classifier: warp per edge; fc1 weights in SMEM
__global__ void k_edge_cls(const int* __restrict__ edges,
                           const float* __restrict__ fc1_w, const float* __restrict__ fc1_b,
                           const float* __restrict__ fc2_w, const float* __restrict__ fc2_b,
                           float* __restrict__ out) {
    __shared__ float s_w1[64 * 32];
    __shared__ float s_b1[32];
    __shared__ float s_w2[64];
    __shared__ float s_b2[2];
    int tid = threadIdx.x;
    for (int i = tid; i < 64 * 32; i += blockDim.x) s_w1[i] = fc1_w[i];
    if (tid < 32) s_b1[tid] = fc1_b[tid];
    if (tid < 64) s_w2[tid] = fc2_w[tid];
    if (tid < 2)  s_b2[tid] = fc2_b[tid];
    __syncthreads();

    int warp = tid >> 5, lane = tid & 31;
    int e = blockIdx.x * (blockDim.x / 32) + warp;
    if (e >= NE) return;
    int s0 = edges[e], d0 = edges[NE + e];
    float plo = g_x2[s0 * OUTC + lane];
    float phi = g_x2[d0 * OUTC + lane];
    float acc = s_b1[lane];
    #pragma unroll
    for (int k = 0; k < 32; k++)
        acc = fmaf(__shfl_sync(0xffffffffu, plo, k), s_w1[k * 32 + lane], acc);
    #pragma unroll
    for (int k = 0; k < 32; k++)
        acc = fmaf(__shfl_sync(0xffffffffu, phi, k), s_w1[(32 + k) * 32 + lane], acc);
    acc = fmaxf(acc, 0.f);
    float z0 = acc * s_w2[lane * 2 + 0];
    float z1 = acc * s_w2[lane * 2 + 1];
    #pragma unroll
    for (int off = 16; off > 0; off >>= 1) {
        z0 += __shfl_down_sync(0xffffffffu, z0, off);
        z1 += __shfl_down_sync(0xffffffffu, z1, off);
    }
    if (lane == 0) {
        z0 += s_b2[0]; z1 += s_b2[1];
        float mm = fmaxf(z0, z1);
        float e0 = expf(z0 - mm), e1 = expf(z1 - mm);
        float inv = 1.f / (e0 + e1);
        out[2 * e]     = e0 * inv;
        out[2 * e + 1] = e1 * inv;
    }
}

// ---------------- launch ----------------------------------------------------
static inline int gdiv(int a, int b) { return (a + b - 1) / b; }

extern "C" void kernel_launch(void* const* d_in, const int* in_sizes, int n_in,
                              void* d_out, int out_size) {
    const float* x        = (const float*)d_in[0];
    const int*   edges    = (const int*)d_in[1];
    const float* ef       = (const float*)d_in[2];
    const float* W1       = (const float*)d_in[3];
    const float* att_src1 = (const float*)d_in[4];
    const float* att_dst1 = (const float*)d_in[5];
    const float* We       = (const float*)d_in[6];
    const float* att_e    = (const float*)d_in[7];
    const float* b1       = (const float*)d_in[8];
    const float* W2       = (const float*)d_in[9];
    const float* att_src2 = (const float*)d_in[10];
    const float* att_dst2 = (const float*)d_in[11];
    const float* b2       = (const float*)d_in[12];
    const float* fc1_w    = (const float*)d_in[13];
    const float* fc1_b    = (const float*)d_in[14];
    const float* fc2_w    = (const float*)d_in[15];
    const float* fc2_b    = (const float*)d_in[16];
    float* out = (float*)d_out;

    float* d_x1; cudaGetSymbolAddress((void**)&d_x1, g_x1);
    float* d_x2; cudaGetSymbolAddress((void**)&d_x2, g_x2);

    const int B = 256;

    // ---- layer 1 ----
    k_init<<<gdiv(NN * HC, B), B>>>();
    k_prep<<<gdiv(NE * EDIM, B), B>>>(edges, ef);
    k_weatt<<<1, 64>>>(We, att_e);
    k_proj<<<gdiv(NN * HC, B), B>>>(x, W1, INF_DIM);
    k_attdot<<<gdiv(NN * HEADS, B), B>>>(att_src1, att_dst1);
    k_alpha<<<gdiv(ET * HEADS, B), B>>>(edges, ef, 1);
    k_exp<<<gdiv(ET * HEADS, B), B>>>(edges);
    k_norm<<<gdiv(ET * HEADS, B), B>>>(edges);
    k_agg<<<gdiv(ET * HC, B), B>>>(edges);
    k_meanbias<<<gdiv(NN * OUTC, B), B>>>(b1, d_x1);

    // ---- layer 2 ----
    k_reinit<<<gdiv(NN * HC, B), B>>>();
    k_proj<<<gdiv(NN * HC, B), B>>>(d_x1, W2, OUTC);
    k_attdot<<<gdiv(NN * HEADS, B), B>>>(att_src2, att_dst2);
    k_alpha<<<gdiv(ET * HEADS, B), B>>>(edges, ef, 0);
    k_exp<<<gdiv(ET * HEADS, B), B>>>(edges);
    k_norm<<<gdiv(ET * HEADS, B), B>>>(edges);
    k_agg<<<gdiv(ET * HC, B), B>>>(edges);
    k_meanbias<<<gdiv(NN * OUTC, B), B>>>(b2, d_x2);

    // ---- classifier ----
    k_fill<<<gdiv(NN * NN * 2 / 4, B), B>>>(fc1_b, fc2_w, fc2_b, out);
    k_edge_cls<<<gdiv(NE, 8), 256>>>(edges, fc1_w, fc1_b, fc2_w, fc2_b, out);
}

// round 2
// speedup vs baseline: 1.5263x; 1.5263x over previous
#include <cuda_runtime.h>
#include <math.h>

#define NN    1500
#define NE    48000
#define ET    (NE + NN)       // edges + self loops = 49500
#define INF_DIM 128
#define OUTC  32
#define HEADS 4
#define HC    128             // HEADS*OUTC
#define EDIM  16

// ---------------- scratch (device globals) ----------------------------------
__device__ float g_cnt[NN];
__device__ float g_easum[NN * EDIM];
__device__ float g_weatt[EDIM * HEADS];     // [d][h]
__device__ float g_h[NN * HC];              // h1 then h2
__device__ float g_as[NN * HEADS];
__device__ float g_ad[NN * HEADS];
__device__ float g_e[ET * HEADS];           // exp(alpha)
__device__ float g_s1[NN * HEADS];
__device__ float g_s2[NN * HEADS];
__device__ float g_agg1[NN * HC];
__device__ float g_agg2[NN * HC];
__device__ float g_x1[NN * OUTC];
__device__ float g_x2[NN * OUTC];

static inline int gdiv(int a, int b) { return (a + b - 1) / b; }

// ---------------- kernels ----------------------------------------------------

// zero all accumulation scratch once (separate buffers per layer -> no reinit)
__global__ void k_init() {
    int i = blockIdx.x * blockDim.x + threadIdx.x;
    if (i < NN * HC) { g_agg1[i] = 0.f; g_agg2[i] = 0.f; }
    if (i < NN)        g_cnt[i] = 0.f;
    if (i < NN * EDIM) g_easum[i] = 0.f;
    if (i < NN * HEADS) { g_s1[i] = 0.f; g_s2[i] = 0.f; }
}

// per-dst edge-feature sums + counts (self-loop attr = mean) ; also We_att
__global__ void k_prep(const int* __restrict__ edges, const float* __restrict__ ef,
                       const float* __restrict__ We, const float* __restrict__ att_e) {
    int t = blockIdx.x * blockDim.x + threadIdx.x;
    // fused tiny precompute: We_att[d][h] = sum_c We[d][h*32+c]*att_e[h][c]
    if (blockIdx.x == 0 && threadIdx.x < EDIM * HEADS) {
        int d = threadIdx.x / HEADS, h = threadIdx.x % HEADS;
        float acc = 0.f;
        #pragma unroll
        for (int c = 0; c < OUTC; c++)
            acc = fmaf(We[d * HC + h * OUTC + c], att_e[h * OUTC + c], acc);
        g_weatt[d * HEADS + h] = acc;
    }
    if (t >= NE) return;
    int dst = edges[NE + t];
    const float4* efr = reinterpret_cast<const float4*>(ef + t * EDIM);
    float4* dstp = reinterpret_cast<float4*>(&g_easum[dst * EDIM]);
    #pragma unroll
    for (int q = 0; q < 4; q++) atomicAdd(&dstp[q], efr[q]);
    atomicAdd(&g_cnt[dst], 1.f);
}

// proj + fused attention dots.
// block: 128 threads (thread j = output column), 4 rows per block.
__global__ void k_proj_att(const float* __restrict__ in, const float* __restrict__ W, int K,
                           const float* __restrict__ a_src, const float* __restrict__ a_dst) {
    __shared__ float xs[4 * INF_DIM];
    int j = threadIdx.x;               // 0..127
    int i0 = blockIdx.x * 4;
    // cooperative load of 4 input rows
    for (int idx = j; idx < 4 * K; idx += 128)
        xs[idx] = in[i0 * K + idx];
    __syncthreads();

    float acc0 = 0.f, acc1 = 0.f, acc2 = 0.f, acc3 = 0.f;
    #pragma unroll 8
    for (int k = 0; k < K; k++) {
        float w = W[k * HC + j];
        acc0 = fmaf(xs[k],           w, acc0);
        acc1 = fmaf(xs[K + k],       w, acc1);
        acc2 = fmaf(xs[2 * K + k],   w, acc2);
        acc3 = fmaf(xs[3 * K + k],   w, acc3);
    }
    g_h[(i0 + 0) * HC + j] = acc0;
    g_h[(i0 + 1) * HC + j] = acc1;
    g_h[(i0 + 2) * HC + j] = acc2;
    g_h[(i0 + 3) * HC + j] = acc3;

    // attention dots: warp w == head w; lane c == channel
    int h = j >> 5, lane = j & 31;
    float asw = a_src[h * OUTC + lane];
    float adw = a_dst[h * OUTC + lane];
    float accs[4] = {acc0, acc1, acc2, acc3};
    #pragma unroll
    for (int r = 0; r < 4; r++) {
        float s = accs[r] * asw;
        float d = accs[r] * adw;
        #pragma unroll
        for (int off = 16; off > 0; off >>= 1) {
            s += __shfl_down_sync(0xffffffffu, s, off);
            d += __shfl_down_sync(0xffffffffu, d, off);
        }
        if (lane == 0) {
            g_as[(i0 + r) * HEADS + h] = s;
            g_ad[(i0 + r) * HEADS + h] = d;
        }
    }
}

// fused alpha + leaky_relu + exp + segment-sum (no max shift; |alpha| is tiny)
// one thread per edge, all 4 heads via float4
__global__ void k_edge(const int* __restrict__ edges, const float* __restrict__ ef,
                       float* __restrict__ s_out, int has_extra) {
    int idx = blockIdx.x * blockDim.x + threadIdx.x;
    if (idx >= ET) return;
    int src, dst;
    float4 extra = make_float4(0.f, 0.f, 0.f, 0.f);
    const float4* wa = reinterpret_cast<const float4*>(g_weatt);
    if (idx < NE) {
        src = edges[idx]; dst = edges[NE + idx];
        if (has_extra) {
            #pragma unroll
            for (int d = 0; d < EDIM; d++) {
                float v = ef[idx * EDIM + d];
                float4 w = wa[d];
                extra.x = fmaf(v, w.x, extra.x);
                extra.y = fmaf(v, w.y, extra.y);
                extra.z = fmaf(v, w.z, extra.z);
                extra.w = fmaf(v, w.w, extra.w);
            }
        }
    } else {
        src = dst = idx - NE;
        if (has_extra) {
            float inv = 1.f / fmaxf(g_cnt[dst], 1.f);
            #pragma unroll
            for (int d = 0; d < EDIM; d++) {
                float v = g_easum[dst * EDIM + d] * inv;
                float4 w = wa[d];
                extra.x = fmaf(v, w.x, extra.x);
                extra.y = fmaf(v, w.y, extra.y);
                extra.z = fmaf(v, w.z, extra.z);
                extra.w = fmaf(v, w.w, extra.w);
            }
        }
    }
    float4 as4 = reinterpret_cast<const float4*>(g_as)[src];
    float4 ad4 = reinterpret_cast<const float4*>(g_ad)[dst];
    float a0 = as4.x + ad4.x + extra.x;
    float a1 = as4.y + ad4.y + extra.y;
    float a2 = as4.z + ad4.z + extra.z;
    float a3 = as4.w + ad4.w + extra.w;
    a0 = (a0 > 0.f) ? a0 : 0.2f * a0;
    a1 = (a1 > 0.f) ? a1 : 0.2f * a1;
    a2 = (a2 > 0.f) ? a2 : 0.2f * a2;
    a3 = (a3 > 0.f) ? a3 : 0.2f * a3;
    float4 e4 = make_float4(expf(a0), expf(a1), expf(a2), expf(a3));
    reinterpret_cast<float4*>(g_e)[idx] = e4;
    atomicAdd(reinterpret_cast<float4*>(&s_out[dst * HEADS]), e4);
}

// normalize + aggregate: one thread per (edge, 4-channel chunk); float4 atomics
__global__ void k_agg(const int* __restrict__ edges, const float* __restrict__ s_in,
                      float* __restrict__ agg) {
    int t = blockIdx.x * blockDim.x + threadIdx.x;
    if (t >= ET * (HC / 4)) return;
    int idx = t / (HC / 4), q = t % (HC / 4);
    int h = q >> 3;                    // 8 float4 chunks per head
    int src, dst;
    if (idx < NE) { src = edges[idx]; dst = edges[NE + idx]; }
    else          { src = dst = idx - NE; }
    float w = g_e[idx * HEADS + h] / s_in[dst * HEADS + h];
    float4 hv = reinterpret_cast<const float4*>(&g_h[src * HC])[q];
    float4 v = make_float4(w * hv.x, w * hv.y, w * hv.z, w * hv.w);
    atomicAdd(&reinterpret_cast<float4*>(&agg[dst * HC])[q], v);
}

// x[i][c] = mean over heads + bias
__global__ void k_meanbias(const float* __restrict__ agg, const float* __restrict__ bias,
                           float* __restrict__ xout) {
    int t = blockIdx.x * blockDim.x + threadIdx.x;
    if (t >= NN * OUTC) return;
    int i = t / OUTC, c = t % OUTC;
    const float* a = agg + i * HC;
    xout[t] = 0.25f * (a[c] + a[OUTC + c] + a[2 * OUTC + c] + a[3 * OUTC + c]) + bias[c];
}

// constant rows [NE, NN*NN): softmax(relu(fc1_b)@fc2_w + fc2_b)
__global__ void k_fill(const float* __restrict__ fc1_b, const float* __restrict__ fc2_w,
                       const float* __restrict__ fc2_b, float* __restrict__ out) {
    const int base = NE * 2 / 4;                 // first float4 to write (24000)
    const int total = NN * NN * 2 / 4;           // 1,125,000
    int t = base + blockIdx.x * blockDim.x + threadIdx.x;
    if (t >= total) return;
    float z0 = fc2_b[0], z1 = fc2_b[1];
    #pragma unroll
    for (int c = 0; c < 32; c++) {
        float hc = fmaxf(fc1_b[c], 0.f);
        z0 = fmaf(hc, fc2_w[c * 2 + 0], z0);
        z1 = fmaf(hc, fc2_w[c * 2 + 1], z1);
    }
    float mm = fmaxf(z0, z1);
    float e0 = expf(z0 - mm), e1 = expf(z1 - mm);
    float inv = 1.f / (e0 + e1);
    reinterpret_cast<float4*>(out)[t] = make_float4(e0 * inv, e1 * inv, e0 * inv, e1 * inv);
}

// per-edge classifier: warp per edge; fc1 weights in SMEM
__global__ void k_edge_cls(const int* __restrict__ edges,
                           const float* __restrict__ fc1_w, const float* __restrict__ fc1_b,
                           const float* __restrict__ fc2_w, const float* __restrict__ fc2_b,
                           float* __restrict__ out) {
    __shared__ float s_w1[64 * 32];
    __shared__ float s_b1[32];
    __shared__ float s_w2[64];
    __shared__ float s_b2[2];
    int tid = threadIdx.x;
    for (int i = tid; i < 64 * 32; i += blockDim.x) s_w1[i] = fc1_w[i];
    if (tid < 32) s_b1[tid] = fc1_b[tid];
    if (tid < 64) s_w2[tid] = fc2_w[tid];
    if (tid < 2)  s_b2[tid] = fc2_b[tid];
    __syncthreads();

    int warp = tid >> 5, lane = tid & 31;
    int e = blockIdx.x * (blockDim.x / 32) + warp;
    if (e >= NE) return;
    int s0 = edges[e], d0 = edges[NE + e];
    float plo = g_x2[s0 * OUTC + lane];
    float phi = g_x2[d0 * OUTC + lane];
    float acc = s_b1[lane];
    #pragma unroll
    for (int k = 0; k < 32; k++)
        acc = fmaf(__shfl_sync(0xffffffffu, plo, k), s_w1[k * 32 + lane], acc);
    #pragma unroll
    for (int k = 0; k < 32; k++)
        acc = fmaf(__shfl_sync(0xffffffffu, phi, k), s_w1[(32 + k) * 32 + lane], acc);
    acc = fmaxf(acc, 0.f);
    float z0 = acc * s_w2[lane * 2 + 0];
    float z1 = acc * s_w2[lane * 2 + 1];
    #pragma unroll
    for (int off = 16; off > 0; off >>= 1) {
        z0 += __shfl_down_sync(0xffffffffu, z0, off);
        z1 += __shfl_down_sync(0xffffffffu, z1, off);
    }
    if (lane == 0) {
        z0 += s_b2[0]; z1 += s_b2[1];
        float mm = fmaxf(z0, z1);
        float e0 = expf(z0 - mm), e1 = expf(z1 - mm);
        float inv = 1.f / (e0 + e1);
        out[2 * e]     = e0 * inv;
        out[2 * e + 1] = e1 * inv;
    }
}

// ---------------- launch ------------------------------------------------------
extern "C" void kernel_launch(void* const* d_in, const int* in_sizes, int n_in,
                              void* d_out, int out_size) {
    const float* x        = (const float*)d_in[0];
    const int*   edges    = (const int*)d_in[1];
    const float* ef       = (const float*)d_in[2];
    const float* W1       = (const float*)d_in[3];
    const float* att_src1 = (const float*)d_in[4];
    const float* att_dst1 = (const float*)d_in[5];
    const float* We       = (const float*)d_in[6];
    const float* att_e    = (const float*)d_in[7];
    const float* b1       = (const float*)d_in[8];
    const float* W2       = (const float*)d_in[9];
    const float* att_src2 = (const float*)d_in[10];
    const float* att_dst2 = (const float*)d_in[11];
    const float* b2       = (const float*)d_in[12];
    const float* fc1_w    = (const float*)d_in[13];
    const float* fc1_b    = (const float*)d_in[14];
    const float* fc2_w    = (const float*)d_in[15];
    const float* fc2_b    = (const float*)d_in[16];
    float* out = (float*)d_out;

    float* d_x1;   cudaGetSymbolAddress((void**)&d_x1, g_x1);
    float* d_x2;   cudaGetSymbolAddress((void**)&d_x2, g_x2);
    float* d_s1;   cudaGetSymbolAddress((void**)&d_s1, g_s1);
    float* d_s2;   cudaGetSymbolAddress((void**)&d_s2, g_s2);
    float* d_agg1; cudaGetSymbolAddress((void**)&d_agg1, g_agg1);
    float* d_agg2; cudaGetSymbolAddress((void**)&d_agg2, g_agg2);

    const int B = 256;

    k_init<<<gdiv(NN * HC, B), B>>>();
    k_prep<<<gdiv(NE, B), B>>>(edges, ef, We, att_e);

    // layer 1
    k_proj_att<<<NN / 4, 128>>>(x, W1, INF_DIM, att_src1, att_dst1);
    k_edge<<<gdiv(ET, B), B>>>(edges, ef, d_s1, 1);
    k_agg<<<gdiv(ET * (HC / 4), B), B>>>(edges, d_s1, d_agg1);
    k_meanbias<<<gdiv(NN * OUTC, B), B>>>(d_agg1, b1, d_x1);

    // layer 2
    k_proj_att<<<NN / 4, 128>>>(d_x1, W2, OUTC, att_src2, att_dst2);
    k_edge<<<gdiv(ET, B), B>>>(edges, ef, d_s2, 0);
    k_agg<<<gdiv(ET * (HC / 4), B), B>>>(edges, d_s2, d_agg2);
    k_meanbias<<<gdiv(NN * OUTC, B), B>>>(d_agg2, b2, d_x2);

    // classifier
    k_fill<<<gdiv(NN * NN * 2 / 4 - NE * 2 / 4, B), B>>>(fc1_b, fc2_w, fc2_b, out);
    k_edge_cls<<<gdiv(NE, 8), 256>>>(edges, fc1_w, fc1_b, fc2_w, fc2_b, out);
}

// round 3
// speedup vs baseline: 1.6925x; 1.1089x over previous
#include <cuda_runtime.h>
#include <math.h>

#define NN    1500
#define NE    48000
#define ET    (NE + NN)       // 49500
#define IND   128
#define OUTC  32
#define HEADS 4
#define HC    128
#define EDIM  16

// ---- one contiguous zeroed scratch block (single memset) -------------------
// layout (floats):
//   cnt   [0,       1500)
//   easum [1500,    25500)
//   s1    [25500,   31500)
//   s2    [31500,   37500)
//   agg1  [37500,   229500)
//   agg2  [229500,  421500)
#define OFF_CNT   0
#define OFF_EASUM 1500
#define OFF_S1    25500
#define OFF_S2    31500
#define OFF_AGG1  37500
#define OFF_AGG2  229500
#define ZTOTAL    421500
__device__ __align__(16) float g_z[ZTOTAL];

// non-zeroed scratch
__device__ float g_weatt[EDIM * HEADS];   // [d][h]
__device__ __align__(16) float g_h[NN * HC];
__device__ __align__(16) float g_as[NN * HEADS];
__device__ __align__(16) float g_ad[NN * HEADS];
__device__ float g_x2[NN * OUTC];

static inline int gdiv(int a, int b) { return (a + b - 1) / b; }

// ---- prep: per-dst edge-feature sums + counts; We_att precompute ----------
__global__ void k_prep(const int* __restrict__ edges, const float* __restrict__ ef,
                       const float* __restrict__ We, const float* __restrict__ att_e) {
    int t = blockIdx.x * blockDim.x + threadIdx.x;
    if (blockIdx.x == 0 && threadIdx.x < EDIM * HEADS) {
        int d = threadIdx.x / HEADS, h = threadIdx.x % HEADS;
        float acc = 0.f;
        #pragma unroll
        for (int c = 0; c < OUTC; c++)
            acc = fmaf(We[d * HC + h * OUTC + c], att_e[h * OUTC + c], acc);
        g_weatt[d * HEADS + h] = acc;
    }
    if (t >= NE) return;
    int dst = edges[NE + t];
    const float4* efr = reinterpret_cast<const float4*>(ef + t * EDIM);
    float4* dp = reinterpret_cast<float4*>(&g_z[OFF_EASUM + dst * EDIM]);
    #pragma unroll
    for (int q = 0; q < 4; q++) atomicAdd(&dp[q], efr[q]);
    atomicAdd(&g_z[OFF_CNT + dst], 1.f);
}

// ---- proj layer 1: 8 rows/block, 256 threads; fused attention dots --------
__global__ void k_proj1(const float* __restrict__ x, const float* __restrict__ W,
                        const float* __restrict__ a_src, const float* __restrict__ a_dst) {
    __shared__ float xs[8 * IND];
    int tid = threadIdx.x;
    int j = tid & 127;            // output column
    int half = tid >> 7;          // 0/1 -> rows [half*4, half*4+4)
    int i0 = blockIdx.x * 8;

    for (int idx = tid; idx < 8 * IND; idx += 256) {
        int r = idx / IND;
        xs[idx] = (i0 + r < NN) ? x[(i0 + r) * IND + (idx % IND)] : 0.f;
    }
    __syncthreads();

    const float* xr = xs + half * 4 * IND;
    float a0 = 0.f, a1 = 0.f, a2 = 0.f, a3 = 0.f;
    #pragma unroll 8
    for (int k = 0; k < IND; k++) {
        float w = W[k * HC + j];
        a0 = fmaf(xr[k],           w, a0);
        a1 = fmaf(xr[IND + k],     w, a1);
        a2 = fmaf(xr[2 * IND + k], w, a2);
        a3 = fmaf(xr[3 * IND + k], w, a3);
    }
    float accs[4] = {a0, a1, a2, a3};

    int h = j >> 5, lane = tid & 31;
    float asw = a_src[h * OUTC + lane];
    float adw = a_dst[h * OUTC + lane];
    #pragma unroll
    for (int r = 0; r < 4; r++) {
        int row = i0 + half * 4 + r;
        if (row < NN) g_h[row * HC + j] = accs[r];
        float s = accs[r] * asw, d = accs[r] * adw;
        #pragma unroll
        for (int off = 16; off > 0; off >>= 1) {
            s += __shfl_down_sync(0xffffffffu, s, off);
            d += __shfl_down_sync(0xffffffffu, d, off);
        }
        if (lane == 0 && row < NN) {
            g_as[row * HEADS + h] = s;
            g_ad[row * HEADS + h] = d;
        }
    }
}

// ---- proj layer 2: input x1 computed on-the-fly from agg1/s1/b1 ------------
__global__ void k_proj2(const float* __restrict__ W,
                        const float* __restrict__ b1,
                        const float* __restrict__ a_src, const float* __restrict__ a_dst) {
    __shared__ float xs[8 * OUTC];
    int tid = threadIdx.x;
    int j = tid & 127;
    int half = tid >> 7;
    int i0 = blockIdx.x * 8;

    // one element per thread: r=tid>>5, c=tid&31
    {
        int r = tid >> 5, c = tid & 31;
        int row = i0 + r;
        float v = 0.f;
        if (row < NN) {
            const float* ag = &g_z[OFF_AGG1 + row * HC];
            const float* sr = &g_z[OFF_S1 + row * HEADS];
            v = 0.25f * (ag[c]            / sr[0] +
                         ag[OUTC + c]     / sr[1] +
                         ag[2 * OUTC + c] / sr[2] +
                         ag[3 * OUTC + c] / sr[3]) + b1[c];
        }
        xs[tid] = v;
    }
    __syncthreads();

    const float* xr = xs + half * 4 * OUTC;
    float a0 = 0.f, a1 = 0.f, a2 = 0.f, a3 = 0.f;
    #pragma unroll
    for (int k = 0; k < OUTC; k++) {
        float w = W[k * HC + j];
        a0 = fmaf(xr[k],            w, a0);
        a1 = fmaf(xr[OUTC + k],     w, a1);
        a2 = fmaf(xr[2 * OUTC + k], w, a2);
        a3 = fmaf(xr[3 * OUTC + k], w, a3);
    }
    float accs[4] = {a0, a1, a2, a3};

    int h = j >> 5, lane = tid & 31;
    float asw = a_src[h * OUTC + lane];
    float adw = a_dst[h * OUTC + lane];
    #pragma unroll
    for (int r = 0; r < 4; r++) {
        int row = i0 + half * 4 + r;
        if (row < NN) g_h[row * HC + j] = accs[r];
        float s = accs[r] * asw, d = accs[r] * adw;
        #pragma unroll
        for (int off = 16; off > 0; off >>= 1) {
            s += __shfl_down_sync(0xffffffffu, s, off);
            d += __shfl_down_sync(0xffffffffu, d, off);
        }
        if (lane == 0 && row < NN) {
            g_as[row * HEADS + h] = s;
            g_ad[row * HEADS + h] = d;
        }
    }
}

// ---- fused edge pass: alpha -> leaky -> exp -> atomic s, atomic agg += e*h --
// warp per edge; normalization deferred (agg holds sum of e*h, divided later)
__global__ void k_edge_agg(const int* __restrict__ edges, const float* __restrict__ ef,
                           float* __restrict__ s_out, float* __restrict__ agg,
                           int has_extra) {
    int gw = (blockIdx.x * blockDim.x + threadIdx.x) >> 5;
    int lane = threadIdx.x & 31;
    if (gw >= ET) return;
    int src, dst;
    if (gw < NE) { src = edges[gw]; dst = edges[NE + gw]; }
    else         { src = dst = gw - NE; }

    int h = lane >> 3;
    float extra = 0.f;
    if (has_extra) {
        if (gw < NE) {
            #pragma unroll
            for (int d = 0; d < EDIM; d++)
                extra = fmaf(ef[gw * EDIM + d], g_weatt[d * HEADS + h], extra);
        } else {
            float inv = 1.f / fmaxf(g_z[OFF_CNT + dst], 1.f);
            #pragma unroll
            for (int d = 0; d < EDIM; d++)
                extra = fmaf(g_z[OFF_EASUM + dst * EDIM + d] * inv,
                             g_weatt[d * HEADS + h], extra);
        }
    }
    float a = g_as[src * HEADS + h] + g_ad[dst * HEADS + h] + extra;
    a = (a > 0.f) ? a : 0.2f * a;
    float e = expf(a);
    if ((lane & 7) == 0) atomicAdd(&s_out[dst * HEADS + h], e);

    float4 hv = reinterpret_cast<const float4*>(&g_h[src * HC])[lane];
    float4 v = make_float4(e * hv.x, e * hv.y, e * hv.z, e * hv.w);
    atomicAdd(&reinterpret_cast<float4*>(&agg[dst * HC])[lane], v);
}

// ---- x2 = mean over heads of agg2/s2 + b2 ----------------------------------
__global__ void k_meanbias2(const float* __restrict__ b2) {
    int t = blockIdx.x * blockDim.x + threadIdx.x;
    if (t >= NN * OUTC) return;
    int i = t / OUTC, c = t % OUTC;
    const float* ag = &g_z[OFF_AGG2 + i * HC];
    const float* sr = &g_z[OFF_S2 + i * HEADS];
    g_x2[t] = 0.25f * (ag[c]            / sr[0] +
                       ag[OUTC + c]     / sr[1] +
                       ag[2 * OUTC + c] / sr[2] +
                       ag[3 * OUTC + c] / sr[3]) + b2[c];
}

// ---- classifier + constant fill, single launch ------------------------------
#define CLS_BLOCKS 6000                         // 8 edges/block * 6000 = 48000
#define FILL_BASE  (NE * 2 / 4)                 // 24000 (float4 units)
#define FILL_TOTAL (NN * NN * 2 / 4)            // 1125000
#define FILL_BLOCKS gdiv_c(FILL_TOTAL - FILL_BASE, 1024)
constexpr int gdiv_c(int a, int b) { return (a + b - 1) / b; }

__global__ void k_cls_fill(const int* __restrict__ edges,
                           const float* __restrict__ fc1_w, const float* __restrict__ fc1_b,
                           const float* __restrict__ fc2_w, const float* __restrict__ fc2_b,
                           float* __restrict__ out) {
    int tid = threadIdx.x;
    if (blockIdx.x >= CLS_BLOCKS) {
        // fill branch: rows >= NE get the constant softmax(relu(fc1_b)@fc2_w+fc2_b)
        float z0 = fc2_b[0], z1 = fc2_b[1];
        #pragma unroll
        for (int c = 0; c < 32; c++) {
            float hc = fmaxf(fc1_b[c], 0.f);
            z0 = fmaf(hc, fc2_w[c * 2 + 0], z0);
            z1 = fmaf(hc, fc2_w[c * 2 + 1], z1);
        }
        float mm = fmaxf(z0, z1);
        float e0 = expf(z0 - mm), e1 = expf(z1 - mm);
        float inv = 1.f / (e0 + e1);
        float4 v = make_float4(e0 * inv, e1 * inv, e0 * inv, e1 * inv);
        int base = FILL_BASE + (blockIdx.x - CLS_BLOCKS) * 1024 + tid;
        #pragma unroll
        for (int k = 0; k < 4; k++) {
            int idx = base + k * 256;
            if (idx < FILL_TOTAL) reinterpret_cast<float4*>(out)[idx] = v;
        }
        return;
    }

    __shared__ float s_w1[64 * 32];
    __shared__ float s_b1[32];
    __shared__ float s_w2[64];
    __shared__ float s_b2[2];
    for (int i = tid; i < 64 * 32; i += blockDim.x) s_w1[i] = fc1_w[i];
    if (tid < 32) s_b1[tid] = fc1_b[tid];
    if (tid < 64) s_w2[tid] = fc2_w[tid];
    if (tid < 2)  s_b2[tid] = fc2_b[tid];
    __syncthreads();

    int warp = tid >> 5, lane = tid & 31;
    int e = blockIdx.x * 8 + warp;
    if (e >= NE) return;
    int s0 = edges[e], d0 = edges[NE + e];
    float plo = g_x2[s0 * OUTC + lane];
    float phi = g_x2[d0 * OUTC + lane];
    float acc = s_b1[lane];
    #pragma unroll
    for (int k = 0; k < 32; k++)
        acc = fmaf(__shfl_sync(0xffffffffu, plo, k), s_w1[k * 32 + lane], acc);
    #pragma unroll
    for (int k = 0; k < 32; k++)
        acc = fmaf(__shfl_sync(0xffffffffu, phi, k), s_w1[(32 + k) * 32 + lane], acc);
    acc = fmaxf(acc, 0.f);
    float z0 = acc * s_w2[lane * 2 + 0];
    float z1 = acc * s_w2[lane * 2 + 1];
    #pragma unroll
    for (int off = 16; off > 0; off >>= 1) {
        z0 += __shfl_down_sync(0xffffffffu, z0, off);
        z1 += __shfl_down_sync(0xffffffffu, z1, off);
    }
    if (lane == 0) {
        z0 += s_b2[0]; z1 += s_b2[1];
        float mm = fmaxf(z0, z1);
        float e0 = expf(z0 - mm), e1 = expf(z1 - mm);
        float inv = 1.f / (e0 + e1);
        out[2 * e]     = e0 * inv;
        out[2 * e + 1] = e1 * inv;
    }
}

// ---- launch ------------------------------------------------------------------
extern "C" void kernel_launch(void* const* d_in, const int* in_sizes, int n_in,
                              void* d_out, int out_size) {
    const float* x        = (const float*)d_in[0];
    const int*   edges    = (const int*)d_in[1];
    const float* ef       = (const float*)d_in[2];
    const float* W1       = (const float*)d_in[3];
    const float* att_src1 = (const float*)d_in[4];
    const float* att_dst1 = (const float*)d_in[5];
    const float* We       = (const float*)d_in[6];
    const float* att_e    = (const float*)d_in[7];
    const float* b1       = (const float*)d_in[8];
    const float* W2       = (const float*)d_in[9];
    const float* att_src2 = (const float*)d_in[10];
    const float* att_dst2 = (const float*)d_in[11];
    const float* b2       = (const float*)d_in[12];
    const float* fc1_w    = (const float*)d_in[13];
    const float* fc1_b    = (const float*)d_in[14];
    const float* fc2_w    = (const float*)d_in[15];
    const float* fc2_b    = (const float*)d_in[16];
    float* out = (float*)d_out;

    float* zbase; cudaGetSymbolAddress((void**)&zbase, g_z);
    cudaMemsetAsync(zbase, 0, ZTOTAL * sizeof(float));

    const int B = 256;

    k_prep<<<gdiv(NE, B), B>>>(edges, ef, We, att_e);

    // layer 1
    k_proj1<<<gdiv(NN, 8), 256>>>(x, W1, att_src1, att_dst1);
    k_edge_agg<<<gdiv(ET * 32, B), B>>>(edges, ef, zbase + OFF_S1, zbase + OFF_AGG1, 1);

    // layer 2 (x1 computed inside proj2)
    k_proj2<<<gdiv(NN, 8), 256>>>(W2, b1, att_src2, att_dst2);
    k_edge_agg<<<gdiv(ET * 32, B), B>>>(edges, ef, zbase + OFF_S2, zbase + OFF_AGG2, 0);
    k_meanbias2<<<gdiv(NN * OUTC, B), B>>>(b2);

    // classifier + constant fill in one launch
    k_cls_fill<<<CLS_BLOCKS + FILL_BLOCKS, 256>>>(edges, fc1_w, fc1_b, fc2_w, fc2_b, out);
}

// round 4
// speedup vs baseline: 1.7782x; 1.0507x over previous
#include <cuda_runtime.h>
#include <math.h>

#define NN    1500
#define NE    48000
#define ET    (NE + NN)       // 49500
#define IND   128
#define OUTC  32
#define HEADS 4
#define HC    128
#define EDIM  16

// ---- one contiguous zeroed scratch block (single memset) -------------------
#define OFF_CNT   0
#define OFF_EASUM 1500
#define OFF_S1    25500
#define OFF_S2    31500
#define OFF_AGG1  37500
#define OFF_AGG2  229500
#define ZTOTAL    421500
__device__ __align__(16) float g_z[ZTOTAL];

// non-zeroed scratch
__device__ float g_weatt[EDIM * HEADS];   // [d][h]
__device__ __align__(16) float g_h[NN * HC];
__device__ __align__(16) float g_as[NN * HEADS];
__device__ __align__(16) float g_ad[NN * HEADS];

static inline int gdiv(int a, int b) { return (a + b - 1) / b; }

// ================= mega kernel A: prep | proj1 | fill =======================
// blocks [0, PREP_B): per-dst edge-feature sums + counts + We_att
// blocks [PREP_B, PREP_B+PROJ_B): x@W1 + attention dots
// blocks [PREP_B+PROJ_B, ...): constant fill of out rows >= NE
#define PREP_B 188        // gdiv(48000,256)
#define PROJ_B 188        // gdiv(1500,8)
#define FILL_BASE  (NE * 2 / 4)          // 24000 float4
#define FILL_TOTAL (NN * NN * 2 / 4)     // 1125000 float4
#define FILL_B 1076       // gdiv(1125000-24000, 1024)

__global__ void k_megaA(const int* __restrict__ edges, const float* __restrict__ ef,
                        const float* __restrict__ We, const float* __restrict__ att_e,
                        const float* __restrict__ x, const float* __restrict__ W1,
                        const float* __restrict__ a_src, const float* __restrict__ a_dst,
                        const float* __restrict__ fc1_b, const float* __restrict__ fc2_w,
                        const float* __restrict__ fc2_b, float* __restrict__ out) {
    __shared__ float xs[8 * IND];
    int tid = threadIdx.x;
    int bx = blockIdx.x;

    if (bx < PREP_B) {
        // ---- prep ----
        if (bx == 0 && tid < EDIM * HEADS) {
            int d = tid / HEADS, h = tid % HEADS;
            float acc = 0.f;
            #pragma unroll
            for (int c = 0; c < OUTC; c++)
                acc = fmaf(We[d * HC + h * OUTC + c], att_e[h * OUTC + c], acc);
            g_weatt[d * HEADS + h] = acc;
        }
        int t = bx * 256 + tid;
        if (t >= NE) return;
        int dst = edges[NE + t];
        const float4* efr = reinterpret_cast<const float4*>(ef + t * EDIM);
        float4* dp = reinterpret_cast<float4*>(&g_z[OFF_EASUM + dst * EDIM]);
        #pragma unroll
        for (int q = 0; q < 4; q++) atomicAdd(&dp[q], efr[q]);
        atomicAdd(&g_z[OFF_CNT + dst], 1.f);
        return;
    }
    if (bx < PREP_B + PROJ_B) {
        // ---- proj1: 8 rows/block ----
        int j = tid & 127;
        int half = tid >> 7;
        int i0 = (bx - PREP_B) * 8;
        for (int idx = tid; idx < 8 * IND; idx += 256) {
            int r = idx / IND;
            xs[idx] = (i0 + r < NN) ? x[(i0 + r) * IND + (idx % IND)] : 0.f;
        }
        __syncthreads();
        const float* xr = xs + half * 4 * IND;
        float a0 = 0.f, a1 = 0.f, a2 = 0.f, a3 = 0.f;
        #pragma unroll 8
        for (int k = 0; k < IND; k++) {
            float w = W1[k * HC + j];
            a0 = fmaf(xr[k],           w, a0);
            a1 = fmaf(xr[IND + k],     w, a1);
            a2 = fmaf(xr[2 * IND + k], w, a2);
            a3 = fmaf(xr[3 * IND + k], w, a3);
        }
        float accs[4] = {a0, a1, a2, a3};
        int h = j >> 5, lane = tid & 31;
        float asw = a_src[h * OUTC + lane];
        float adw = a_dst[h * OUTC + lane];
        #pragma unroll
        for (int r = 0; r < 4; r++) {
            int row = i0 + half * 4 + r;
            if (row < NN) g_h[row * HC + j] = accs[r];
            float s = accs[r] * asw, d = accs[r] * adw;
            #pragma unroll
            for (int off = 16; off > 0; off >>= 1) {
                s += __shfl_down_sync(0xffffffffu, s, off);
                d += __shfl_down_sync(0xffffffffu, d, off);
            }
            if (lane == 0 && row < NN) {
                g_as[row * HEADS + h] = s;
                g_ad[row * HEADS + h] = d;
            }
        }
        return;
    }
    // ---- fill ----
    {
        float z0 = fc2_b[0], z1 = fc2_b[1];
        #pragma unroll
        for (int c = 0; c < 32; c++) {
            float hc = fmaxf(fc1_b[c], 0.f);
            z0 = fmaf(hc, fc2_w[c * 2 + 0], z0);
            z1 = fmaf(hc, fc2_w[c * 2 + 1], z1);
        }
        float mm = fmaxf(z0, z1);
        float e0 = expf(z0 - mm), e1 = expf(z1 - mm);
        float inv = 1.f / (e0 + e1);
        float4 v = make_float4(e0 * inv, e1 * inv, e0 * inv, e1 * inv);
        int base = FILL_BASE + (bx - PREP_B - PROJ_B) * 1024 + tid;
        #pragma unroll
        for (int k = 0; k < 4; k++) {
            int idx = base + k * 256;
            if (idx < FILL_TOTAL) reinterpret_cast<float4*>(out)[idx] = v;
        }
    }
}

// ================= fused edge pass (warp per edge) ==========================
__global__ void k_edge_agg(const int* __restrict__ edges, const float* __restrict__ ef,
                           float* __restrict__ s_out, float* __restrict__ agg,
                           int has_extra) {
    int gw = (blockIdx.x * blockDim.x + threadIdx.x) >> 5;
    int lane = threadIdx.x & 31;
    if (gw >= ET) return;
    int src, dst;
    if (gw < NE) { src = edges[gw]; dst = edges[NE + gw]; }
    else         { src = dst = gw - NE; }

    int h = lane >> 3;
    float extra = 0.f;
    if (has_extra) {
        if (gw < NE) {
            #pragma unroll
            for (int d = 0; d < EDIM; d++)
                extra = fmaf(ef[gw * EDIM + d], g_weatt[d * HEADS + h], extra);
        } else {
            float inv = 1.f / fmaxf(g_z[OFF_CNT + dst], 1.f);
            #pragma unroll
            for (int d = 0; d < EDIM; d++)
                extra = fmaf(g_z[OFF_EASUM + dst * EDIM + d] * inv,
                             g_weatt[d * HEADS + h], extra);
        }
    }
    float a = g_as[src * HEADS + h] + g_ad[dst * HEADS + h] + extra;
    a = (a > 0.f) ? a : 0.2f * a;
    float e = expf(a);
    if ((lane & 7) == 0) atomicAdd(&s_out[dst * HEADS + h], e);

    float4 hv = reinterpret_cast<const float4*>(&g_h[src * HC])[lane];
    float4 v = make_float4(e * hv.x, e * hv.y, e * hv.z, e * hv.w);
    atomicAdd(&reinterpret_cast<float4*>(&agg[dst * HC])[lane], v);
}

// ================= proj2: 4 rows x 128 cols = 512 threads ===================
__global__ void __launch_bounds__(512) k_proj2(const float* __restrict__ W,
                        const float* __restrict__ b1,
                        const float* __restrict__ a_src, const float* __restrict__ a_dst) {
    __shared__ float xs[4 * OUTC];
    int tid = threadIdx.x;
    int i0 = blockIdx.x * 4;
    // x1 for 4 rows computed by threads 0..127
    if (tid < 128) {
        int r = tid >> 5, c = tid & 31;
        int row = i0 + r;
        const float* ag = &g_z[OFF_AGG1 + row * HC];
        float4 sv = *reinterpret_cast<const float4*>(&g_z[OFF_S1 + row * HEADS]);
        xs[tid] = 0.25f * (ag[c] / sv.x + ag[OUTC + c] / sv.y +
                           ag[2 * OUTC + c] / sv.z + ag[3 * OUTC + c] / sv.w) + b1[c];
    }
    __syncthreads();

    int row_l = tid >> 7;          // 0..3
    int j = tid & 127;
    int row = i0 + row_l;
    const float* xr = xs + row_l * OUTC;
    float acc = 0.f;
    #pragma unroll
    for (int k = 0; k < OUTC; k++)
        acc = fmaf(xr[k], W[k * HC + j], acc);
    g_h[row * HC + j] = acc;

    int h = j >> 5, lane = tid & 31;
    float s = acc * a_src[h * OUTC + lane];
    float d = acc * a_dst[h * OUTC + lane];
    #pragma unroll
    for (int off = 16; off > 0; off >>= 1) {
        s += __shfl_down_sync(0xffffffffu, s, off);
        d += __shfl_down_sync(0xffffffffu, d, off);
    }
    if (lane == 0) {
        g_as[row * HEADS + h] = s;
        g_ad[row * HEADS + h] = d;
    }
}

// ================= classifier with on-the-fly x2 ============================
__device__ __forceinline__ float x2_val(int node, int c, const float* __restrict__ b2) {
    const float* ag = &g_z[OFF_AGG2 + node * HC];
    float4 sv = *reinterpret_cast<const float4*>(&g_z[OFF_S2 + node * HEADS]);
    return 0.25f * (ag[c] / sv.x + ag[OUTC + c] / sv.y +
                    ag[2 * OUTC + c] / sv.z + ag[3 * OUTC + c] / sv.w) + b2[c];
}

__global__ void k_cls(const int* __restrict__ edges,
                      const float* __restrict__ fc1_w, const float* __restrict__ fc1_b,
                      const float* __restrict__ fc2_w, const float* __restrict__ fc2_b,
                      const float* __restrict__ b2, float* __restrict__ out) {
    __shared__ float s_w1[64 * 32];
    __shared__ float s_b1[32];
    __shared__ float s_w2[64];
    __shared__ float s_b2[2];
    int tid = threadIdx.x;
    for (int i = tid; i < 64 * 32; i += blockDim.x) s_w1[i] = fc1_w[i];
    if (tid < 32) s_b1[tid] = fc1_b[tid];
    if (tid < 64) s_w2[tid] = fc2_w[tid];
    if (tid < 2)  s_b2[tid] = fc2_b[tid];
    __syncthreads();

    int warp = tid >> 5, lane = tid & 31;
    int e = blockIdx.x * 8 + warp;
    if (e >= NE) return;
    int s0 = edges[e], d0 = edges[NE + e];
    float plo = x2_val(s0, lane, b2);
    float phi = x2_val(d0, lane, b2);
    float acc = s_b1[lane];
    #pragma unroll
    for (int k = 0; k < 32; k++)
        acc = fmaf(__shfl_sync(0xffffffffu, plo, k), s_w1[k * 32 + lane], acc);
    #pragma unroll
    for (int k = 0; k < 32; k++)
        acc = fmaf(__shfl_sync(0xffffffffu, phi, k), s_w1[(32 + k) * 32 + lane], acc);
    acc = fmaxf(acc, 0.f);
    float z0 = acc * s_w2[lane * 2 + 0];
    float z1 = acc * s_w2[lane * 2 + 1];
    #pragma unroll
    for (int off = 16; off > 0; off >>= 1) {
        z0 += __shfl_down_sync(0xffffffffu, z0, off);
        z1 += __shfl_down_sync(0xffffffffu, z1, off);
    }
    if (lane == 0) {
        z0 += s_b2[0]; z1 += s_b2[1];
        float mm = fmaxf(z0, z1);
        float e0 = expf(z0 - mm), e1 = expf(z1 - mm);
        float inv = 1.f / (e0 + e1);
        out[2 * e]     = e0 * inv;
        out[2 * e + 1] = e1 * inv;
    }
}

// ---- launch ------------------------------------------------------------------
extern "C" void kernel_launch(void* const* d_in, const int* in_sizes, int n_in,
                              void* d_out, int out_size) {
    const float* x        = (const float*)d_in[0];
    const int*   edges    = (const int*)d_in[1];
    const float* ef       = (const float*)d_in[2];
    const float* W1       = (const float*)d_in[3];
    const float* att_src1 = (const float*)d_in[4];
    const float* att_dst1 = (const float*)d_in[5];
    const float* We       = (const float*)d_in[6];
    const float* att_e    = (const float*)d_in[7];
    const float* b1       = (const float*)d_in[8];
    const float* W2       = (const float*)d_in[9];
    const float* att_src2 = (const float*)d_in[10];
    const float* att_dst2 = (const float*)d_in[11];
    const float* b2       = (const float*)d_in[12];
    const float* fc1_w    = (const float*)d_in[13];
    const float* fc1_b    = (const float*)d_in[14];
    const float* fc2_w    = (const float*)d_in[15];
    const float* fc2_b    = (const float*)d_in[16];
    float* out = (float*)d_out;

    float* zbase; cudaGetSymbolAddress((void**)&zbase, g_z);
    cudaMemsetAsync(zbase, 0, ZTOTAL * sizeof(float));

    const int B = 256;

    // prep | proj1 | fill in one launch
    k_megaA<<<PREP_B + PROJ_B + FILL_B, 256>>>(edges, ef, We, att_e, x, W1,
                                               att_src1, att_dst1,
                                               fc1_b, fc2_w, fc2_b, out);

    k_edge_agg<<<gdiv(ET * 32, B), B>>>(edges, ef, zbase + OFF_S1, zbase + OFF_AGG1, 1);
    k_proj2<<<NN / 4, 512>>>(W2, b1, att_src2, att_dst2);
    k_edge_agg<<<gdiv(ET * 32, B), B>>>(edges, ef, zbase + OFF_S2, zbase + OFF_AGG2, 0);
    k_cls<<<NE / 8, 256>>>(edges, fc1_w, fc1_b, fc2_w, fc2_b, b2, out);
}